// round 16
// baseline (speedup 1.0000x reference)
#include <cuda_runtime.h>
#include <math.h>

#define B 8
#define M 12
#define NN 32
#define D 256
#define C 1024      // N*N
#define CH 512      // C/R
#define BM 96
#define GRID 148
#define NT 512

typedef unsigned long long ull;

// Scratch (allocation-free rule: device globals)
__device__ float g_S[BM * NN];     // row sums per bm
__device__ float g_U[NN * CH];     // [n][o] collapsed-GEMM1 weights
__device__ float g_cov[BM * C];    // centered cov (sign -> mask)
__device__ unsigned g_bcnt;        // barrier counter (returns to 0 each barrier)
__device__ int g_bgen;             // barrier generation (monotonic; replay-safe)

// ---- packed f32x2 helpers -------------------------------------------------
__device__ __forceinline__ ull ffma2(ull a, ull b, ull c) {
    ull d_;
    asm("fma.rn.f32x2 %0, %1, %2, %3;" : "=l"(d_) : "l"(a), "l"(b), "l"(c));
    return d_;
}
__device__ __forceinline__ ull pk2(float lo, float hi) {
    ull r;
    asm("mov.b64 %0, {%1, %2};" : "=l"(r) : "f"(lo), "f"(hi));
    return r;
}
__device__ __forceinline__ float unpk_add(ull v) {
    float lo, hi;
    asm("mov.b64 {%0, %1}, %2;" : "=f"(lo), "=f"(hi) : "l"(v));
    return lo + hi;
}
__device__ __forceinline__ void unpk2(ull v, float& lo, float& hi) {
    asm("mov.b64 {%0, %1}, %2;" : "=f"(lo), "=f"(hi) : "l"(v));
}

// smem swizzle: q in [0,128) float4 units within a 512-float row
#define SWZ(q) (((q) & 0x70) | (((q) ^ ((q) >> 4)) & 0x0F))
#define SWZ4(o) (SWZ((o) >> 2) * 4 + ((o) & 3))
#define XPAD 260   // floats per padded x row (= 65 float4)

// Grid-wide generation barrier. Safe: grid == 148 == one full wave; flag is
// monotonic so any number of barriers per launch and graph replays are fine.
__device__ __forceinline__ void gbar() {
    __syncthreads();
    if (threadIdx.x == 0) {
        __threadfence();
        const int old = atomicAdd(&g_bgen, 0);   // read BEFORE arriving
        if (atomicAdd(&g_bcnt, 1) == GRID - 1) {
            g_bcnt = 0;
            __threadfence();
            atomicExch(&g_bgen, old + 1);
        } else {
            while (atomicAdd(&g_bgen, 0) == old) __nanosleep(32);
        }
        __threadfence();
    }
    __syncthreads();
}

// ---------------------------------------------------------------------------
__global__ void __launch_bounds__(NT) kFused(const float* __restrict__ x,
                                             const float* __restrict__ W1,
                                             const float* __restrict__ W2,
                                             float* __restrict__ out) {
    extern __shared__ float sm[];
    const int bid = blockIdx.x;
    const int tid = threadIdx.x;
    const int w = tid >> 5, lane = tid & 31;

    // ======================= PHASE A =======================
    if (bid < BM) {
        // ---- per-bm: one x pass -> S + full 32x32 centered cov ----
        const int bm = bid;
        const int g = w >> 3, wg = w & 7;
        float* xs  = sm;             // padded natural [n*XPAD + d], 8320
        float* red = sm + 8320;      // 16 warps x 512 = 8192
        float* sp  = sm + 16512;     // 256
        float* S   = sm + 16768;     // 32

        const float4* xg4 = (const float4*)(x + (size_t)bm * (NN * D));
        float4* xs4 = (float4*)xs;
        #pragma unroll
        for (int t = 0; t < 4; t++) {
            const int i = tid + t * NT;
            const int n = i >> 6, q = i & 63;
            xs4[n * 65 + q] = xg4[i];    // conflict-free STS.128
        }
        __syncthreads();

        // xk = x[k=lane][wg*32 .. wg*32+31] via 8 LDS.128
        ull xk2[16];
        float spv = 0.f;
        const float4* xrow4 = (const float4*)(xs + lane * XPAD + wg * 32);
        #pragma unroll
        for (int j = 0; j < 8; j++) {
            const float4 v = xrow4[j];
            xk2[2 * j]     = pk2(v.x, v.y);
            xk2[2 * j + 1] = pk2(v.z, v.w);
            spv += (v.x + v.y) + (v.z + v.w);
        }
        if (g == 0) sp[wg * 32 + lane] = spv;
        __syncthreads();
        if (tid < 32) {
            float s = 0.f;
            #pragma unroll
            for (int ww = 0; ww < 8; ww++) s += sp[ww * 32 + tid];
            S[tid] = s;
            g_S[bm * NN + tid] = s;
        }
        __syncthreads();

        // cov partials for n in [g*16, g*16+16)
        ull acc2[16];
        #pragma unroll
        for (int nn = 0; nn < 16; nn++) acc2[nn] = 0ull;

        const ulonglong2* xs2 = (const ulonglong2*)xs;   // rows stride 65 f4
        #pragma unroll
        for (int nn = 0; nn < 16; nn++) {
            const ulonglong2* rowp = xs2 + (g * 16 + nn) * 65 + wg * 8;
            #pragma unroll
            for (int jj = 0; jj < 8; jj++) {
                const ulonglong2 bv = rowp[jj];          // broadcast LDS.128
                acc2[nn] = ffma2(bv.x, xk2[2 * jj], acc2[nn]);
                acc2[nn] = ffma2(bv.y, xk2[2 * jj + 1], acc2[nn]);
            }
        }
        #pragma unroll
        for (int nn = 0; nn < 16; nn++)
            red[w * 512 + nn * 32 + lane] = unpk_add(acc2[nn]);
        __syncthreads();

        if (tid < 256) {   // combine 8 d-chunk partials of the right group
            const float4* red4 = (const float4*)red;
            const int n = tid >> 3, kq = tid & 7;
            const int gn = n >> 4, nl = n & 15;
            float4 cv = make_float4(0.f, 0.f, 0.f, 0.f);
            #pragma unroll
            for (int ww = 0; ww < 8; ww++) {
                const float4 t = red4[(gn * 8 + ww) * 128 + nl * 8 + kq];
                cv.x += t.x; cv.y += t.y; cv.z += t.z; cv.w += t.w;
            }
            const int k0 = kq * 4;
            const float sn = S[n] * (1.f / 256.f);
            cv.x -= sn * S[k0 + 0]; cv.y -= sn * S[k0 + 1];
            cv.z -= sn * S[k0 + 2]; cv.w -= sn * S[k0 + 3];
            ((float4*)(g_cov + (size_t)bm * C))[tid] = cv;
        }
    } else {
        // ---- U blocks (52): o-chunks of 10 ----
        const int ub = bid - BM;
        float* smT = sm + w * 1056;   // per-warp 33x32 transpose buf

        if (w < 10) {
            const int o = ub * 10 + w;
            if (o < CH) {
                const float* row = W1 + (size_t)o * C;
                float rr[32], cs = 0.f;
                #pragma unroll
                for (int j = 0; j < 32; j++) { rr[j] = row[j * 32 + lane]; cs += rr[j]; }
                #pragma unroll
                for (int j = 0; j < 32; j++) smT[j * 33 + lane] = rr[j];
                __syncwarp();
                float rs = 0.f;
                #pragma unroll
                for (int mm = 0; mm < 32; mm++) rs += smT[lane * 33 + mm];
                const float dg = smT[lane * 33 + lane];
                g_U[lane * CH + o] = rs + 2.f * cs - dg;   // lane = n
            }
        }
    }

    gbar();   // single grid barrier: cov + S + U all published

    // ============ PHASE B: e2 + softmax + AV (blocks 0..127) ============
    if (bid < 128) {
        const int ct = bid >> 3, b = bid & 7;
        float* W2s    = sm;                  // 64 x 512 swizzled = 32768
        float* hs     = sm + 32768;          // 12 x 512 swizzled = 6144
        float* S12t   = sm + 38912;          // [n*12 + m], 384
        float* att_sm = sm + 39296;          // [m*64 + cc], 768
        float* rinv   = sm + 40064;          // 24 (+pad)

        const float4* w2g = (const float4*)(W2 + (size_t)(ct * 64) * CH);

        #pragma unroll
        for (int t = 0; t < 16; t++) {       // full 64-row tile, one pass
            const int i = tid + t * NT;
            const int r = i >> 7, q = i & 127;
            ((float4*)W2s)[r * 128 + SWZ(q)] = w2g[i];
        }
        if (tid < 384) {
            const int m = tid >> 5, n = tid & 31;
            S12t[n * 12 + m] = g_S[(b * M + m) * NN + n];
        }
        __syncthreads();

        // h inline: thread owns o = tid
        {
            ull hacc[6];
            #pragma unroll
            for (int mm = 0; mm < 6; mm++) hacc[mm] = 0ull;
            #pragma unroll 4
            for (int n = 0; n < 32; n++) {
                const float u = g_U[n * CH + tid];
                const ull uu = pk2(u, u);
                #pragma unroll
                for (int mm = 0; mm < 6; mm++) {
                    const ull sv = *(const ull*)(S12t + n * 12 + 2 * mm);
                    hacc[mm] = ffma2(sv, uu, hacc[mm]);
                }
            }
            const int so = SWZ4(tid);
            #pragma unroll
            for (int mm = 0; mm < 6; mm++) {
                float a, bb;
                unpk2(hacc[mm], a, bb);
                hs[(2 * mm) * 512 + so]     = fmaxf(a  * (1.f / 512.f), 0.f);
                hs[(2 * mm + 1) * 512 + so] = fmaxf(bb * (1.f / 512.f), 0.f);
            }
        }
        __syncthreads();

        const int c  = tid >> 3;          // 0..63 (row of W2 tile)
        const int kc = tid & 7;           // k-chunk of 64 floats
        const int kc16 = kc * 16;
        const ulonglong2* hu = (const ulonglong2*)hs;
        const ulonglong2* Wu = (const ulonglong2*)W2s;

        ull acc[12];
        #pragma unroll
        for (int m = 0; m < 12; m++) acc[m] = 0ull;

        #pragma unroll 4
        for (int j = 0; j < 16; j++) {
            const int qs = kc16 + ((j ^ kc) & 15);
            const ulonglong2 wv = Wu[c * 128 + qs];
            #pragma unroll
            for (int m = 0; m < 12; m++) {
                const ulonglong2 hv = hu[m * 128 + qs];
                acc[m] = ffma2(wv.x, hv.x, acc[m]);
                acc[m] = ffma2(wv.y, hv.y, acc[m]);
            }
        }
        __syncthreads();   // done with W2s; reuse as partials

        float* part = W2s;   // [kc][c*12+m], stride 771
        #pragma unroll
        for (int m = 0; m < 12; m++)
            part[kc * 771 + c * 12 + m] = unpk_add(acc[m]);
        __syncthreads();

        // combine -> sigmoid -> mask -> exp -> att_sm[m*64 + cc]
        #pragma unroll
        for (int t = 0; t < 2; t++) {
            const int i2 = tid + t * NT;        // = cc*12 + m, cc in 0..63
            if (i2 < 768) {
                const int cc = i2 / 12, m = i2 - 12 * cc;
                float e2v = 0.f;
                #pragma unroll
                for (int kk = 0; kk < 8; kk++) e2v += part[kk * 771 + i2];
                const float cvv = g_cov[(size_t)(b * M + m) * C + ct * 64 + cc];
                const float sg = 1.f / (1.f + __expf(-e2v));
                att_sm[m * 64 + cc] = (cvv > 0.f) ? __expf(sg) : 0.f;
            }
        }
        __syncthreads();

        // row sums -> inverses: 24 rows (m, nl), 16 warps, 2 rounds
        #pragma unroll
        for (int it = 0; it < 2; it++) {
            const int row = it * 16 + w;
            if (row < 24) {
                const int m = row >> 1, nl = row & 1;
                float v = att_sm[m * 64 + nl * 32 + lane];
                #pragma unroll
                for (int off = 16; off; off >>= 1)
                    v += __shfl_xor_sync(0xffffffffu, v, off);
                if (lane == 0) rinv[row] = 1.f / v;
            }
        }
        __syncthreads();

        // AV: row (m, nl) -> out[bm][2ct+nl][:]; lane owns d-chunks lane, lane+32
        #pragma unroll
        for (int it = 0; it < 2; it++) {
            const int row = it * 16 + w;
            if (row < 24) {
                const int m = row >> 1, nl = row & 1;
                const int bm = b * M + m;
                const float av = att_sm[m * 64 + nl * 32 + lane] * rinv[row];
                const float4* xr4 = (const float4*)(x + (size_t)bm * (NN * D));
                float4 a0 = make_float4(0.f, 0.f, 0.f, 0.f);
                float4 a1 = make_float4(0.f, 0.f, 0.f, 0.f);
                #pragma unroll 8
                for (int k = 0; k < NN; k++) {
                    const float ak = __shfl_sync(0xffffffffu, av, k);
                    const float4 xa = xr4[k * 64 + lane];        // L2-warm
                    const float4 xb = xr4[k * 64 + 32 + lane];
                    a0.x += ak * xa.x; a0.y += ak * xa.y;
                    a0.z += ak * xa.z; a0.w += ak * xa.w;
                    a1.x += ak * xb.x; a1.y += ak * xb.y;
                    a1.z += ak * xb.z; a1.w += ak * xb.w;
                }
                float4* o4 = (float4*)(out + ((size_t)bm * NN + 2 * ct + nl) * D);
                o4[lane]      = a0;
                o4[lane + 32] = a1;
            }
        }
    }
}

// ---------------------------------------------------------------------------
extern "C" void kernel_launch(void* const* d_in, const int* in_sizes, int n_in,
                              void* d_out, int out_size) {
    const float* x  = (const float*)d_in[0];
    const float* W1 = (const float*)d_in[1];
    const float* W2 = (const float*)d_in[2];
    float* out = (float*)d_out;

    const int smem = 40096 * sizeof(float);   // 160,384 B (phase-B high-water)
    cudaFuncSetAttribute(kFused, cudaFuncAttributeMaxDynamicSharedMemorySize, smem);

    kFused<<<GRID, NT, smem>>>(x, W1, W2, out);
}